// round 1
// baseline (speedup 1.0000x reference)
#include <cuda_runtime.h>
#include <math.h>

// SlotAttention on GB300 — Round 0: correct fp32 SIMT implementation.
// Structure: ln_stats -> fused-LN KV GEMMs -> 3x(slot iteration) -> final attn.
// All scratch in __device__ globals (no allocations). All launches on the
// default stream, graph-capturable, deterministic (no atomics).

#define Bb 64
#define Nn 4096
#define Dd 256
#define Kk 15
#define Hh 512
#define BN_TOT (Bb * Nn)   // 262144
#define BK_TOT (Bb * Kk)   // 960
#define NBLK 32            // logits n-blocks per batch (4096/128)

// ---------------- scratch (static device memory) ----------------
__device__ float g_mean[BN_TOT];
__device__ float g_rstd[BN_TOT];
__device__ float g_k[(size_t)BN_TOT * Dd];     // 256 MiB
__device__ float g_v[(size_t)BN_TOT * Dd];     // 256 MiB
__device__ float g_slots[BK_TOT * Dd];
__device__ float g_slots_prev[BK_TOT * Dd];
__device__ float g_sln[BK_TOT * Dd];
__device__ float g_q[BK_TOT * Dd];
__device__ float g_attn[(size_t)Bb * Kk * Nn]; // 15.7 MB
__device__ float g_part[Bb * Kk * NBLK];
__device__ float g_invsum[BK_TOT];
__device__ float g_updpart[8 * BK_TOT * Dd];   // 8 n-chunks
__device__ float g_updates[BK_TOT * Dd];
__device__ float g_gi[BK_TOT * 3 * Dd];
__device__ float g_gh[BK_TOT * 3 * Dd];
__device__ float g_h1[BK_TOT * Hh];

// ---------------- helpers ----------------
__device__ __forceinline__ float warp_sum(float v) {
#pragma unroll
    for (int o = 16; o > 0; o >>= 1) v += __shfl_xor_sync(0xffffffffu, v, o);
    return v;
}
__device__ __forceinline__ float sigmoidf_(float x) { return 1.0f / (1.0f + expf(-x)); }

// ---------------- LN row stats over inputs ----------------
// grid: BN_TOT/8, block (32,8)
__global__ void ln_stats_kernel(const float* __restrict__ x) {
    int row = blockIdx.x * 8 + threadIdx.y;
    int lane = threadIdx.x;
    const float* xr = x + (size_t)row * Dd;
    float s = 0.f, s2 = 0.f;
#pragma unroll
    for (int j = 0; j < 8; j++) {
        float v = xr[j * 32 + lane];
        s += v; s2 += v * v;
    }
    s = warp_sum(s); s2 = warp_sum(s2);
    if (lane == 0) {
        float m = s * (1.0f / 256.0f);
        float var = s2 * (1.0f / 256.0f) - m * m;
        g_mean[row] = m;
        g_rstd[row] = rsqrtf(var + 1e-5f);
    }
}

// ---------------- fused LN + projection GEMM (K or V) ----------------
// out[m][j] = dot(LN(x[m]), W[j])   m in [0,BN), j in [0,256)
// grid: (BN_TOT/64, 2); block 256. BM=64, BN=128, BK=16, TM=4, TN=8.
__global__ __launch_bounds__(256) void kv_gemm_kernel(
    const float* __restrict__ x, const float* __restrict__ W,
    const float* __restrict__ lnw, const float* __restrict__ lnb,
    float* __restrict__ out)
{
    __shared__ float As[16][68];    // [k][m] transposed
    __shared__ float Bs[16][132];   // [k][n] transposed

    int m0 = blockIdx.x * 64;
    int n0 = blockIdx.y * 128;
    int tid = threadIdx.x;
    int row_t = tid >> 4;           // 0..15 -> 4 rows each
    int col_t = tid & 15;           // 0..15 -> 8 cols each (split 4+4)

    int ar = tid >> 2;              // 0..63  A-stage row
    int ak = (tid & 3) << 2;        // 0,4,8,12
    int bj = tid >> 1;              // 0..127 B-stage col
    int bk = (tid & 1) << 3;        // 0,8

    float m_r = g_mean[m0 + ar];
    float rs_r = g_rstd[m0 + ar];

    float acc[4][8];
#pragma unroll
    for (int i = 0; i < 4; i++)
#pragma unroll
        for (int j = 0; j < 8; j++) acc[i][j] = 0.f;

    for (int kb = 0; kb < 16; kb++) {
        int k0 = kb * 16;
        // stage A (apply LayerNorm on load)
        float4 xa = *(const float4*)(x + (size_t)(m0 + ar) * Dd + k0 + ak);
        float4 wv = *(const float4*)(lnw + k0 + ak);
        float4 bv = *(const float4*)(lnb + k0 + ak);
        As[ak + 0][ar] = (xa.x - m_r) * rs_r * wv.x + bv.x;
        As[ak + 1][ar] = (xa.y - m_r) * rs_r * wv.y + bv.y;
        As[ak + 2][ar] = (xa.z - m_r) * rs_r * wv.z + bv.z;
        As[ak + 3][ar] = (xa.w - m_r) * rs_r * wv.w + bv.w;
        // stage B (transpose W tile)
#pragma unroll
        for (int h = 0; h < 2; h++) {
            float4 wb = *(const float4*)(W + (size_t)(n0 + bj) * Dd + k0 + bk + h * 4);
            Bs[bk + h * 4 + 0][bj] = wb.x;
            Bs[bk + h * 4 + 1][bj] = wb.y;
            Bs[bk + h * 4 + 2][bj] = wb.z;
            Bs[bk + h * 4 + 3][bj] = wb.w;
        }
        __syncthreads();
#pragma unroll
        for (int k = 0; k < 16; k++) {
            float4 a4 = *(const float4*)&As[k][row_t * 4];
            float4 b0 = *(const float4*)&Bs[k][col_t * 4];
            float4 b1 = *(const float4*)&Bs[k][col_t * 4 + 64];
            float a[4] = {a4.x, a4.y, a4.z, a4.w};
            float bb[8] = {b0.x, b0.y, b0.z, b0.w, b1.x, b1.y, b1.z, b1.w};
#pragma unroll
            for (int i = 0; i < 4; i++)
#pragma unroll
                for (int j = 0; j < 8; j++) acc[i][j] += a[i] * bb[j];
        }
        __syncthreads();
    }
#pragma unroll
    for (int i = 0; i < 4; i++) {
        float* orow = out + (size_t)(m0 + row_t * 4 + i) * Dd + n0;
        *(float4*)(orow + col_t * 4) =
            make_float4(acc[i][0], acc[i][1], acc[i][2], acc[i][3]);
        *(float4*)(orow + col_t * 4 + 64) =
            make_float4(acc[i][4], acc[i][5], acc[i][6], acc[i][7]);
    }
}

// ---------------- slots init ----------------
__global__ void slots_init_kernel(const float* __restrict__ mu,
                                  const float* __restrict__ ls,
                                  const float* __restrict__ noise) {
    int i = blockIdx.x * 256 + threadIdx.x;   // < BK_TOT*Dd
    int kd = i % (Kk * Dd);
    g_slots[i] = mu[kd] + expf(ls[kd]) * noise[i];
}

// ---------------- generic row LayerNorm (M x 256) ----------------
// grid: M/8, block (32,8)
__global__ void ln_apply_kernel(const float* __restrict__ x, float* __restrict__ y,
                                const float* __restrict__ w, const float* __restrict__ bb,
                                int M) {
    int row = blockIdx.x * 8 + threadIdx.y;
    if (row >= M) return;
    int lane = threadIdx.x;
    const float* xr = x + (size_t)row * Dd;
    float v[8];
    float s = 0.f, s2 = 0.f;
#pragma unroll
    for (int j = 0; j < 8; j++) {
        v[j] = xr[j * 32 + lane];
        s += v[j]; s2 += v[j] * v[j];
    }
    s = warp_sum(s); s2 = warp_sum(s2);
    float m = s * (1.0f / 256.0f);
    float rs = rsqrtf(s2 * (1.0f / 256.0f) - m * m + 1e-5f);
    float* yr = y + (size_t)row * Dd;
#pragma unroll
    for (int j = 0; j < 8; j++) {
        int dd = j * 32 + lane;
        yr[dd] = (v[j] - m) * rs * w[dd] + bb[dd];
    }
}

// ---------------- small GEMM: C[M][Nc] = A[M][Kc] @ W[Nc][Kc]^T (+bias)(+res)(relu) ----------------
// grid (M/64, Nc/64); block 256. mode bits: 1=bias, 2=relu, 4=residual
__global__ __launch_bounds__(256) void small_gemm_kernel(
    const float* __restrict__ A, const float* __restrict__ W,
    const float* __restrict__ bias, const float* __restrict__ res,
    float* __restrict__ C, int Kc, int Nc, int mode)
{
    __shared__ float As[16][68];
    __shared__ float Bs[16][68];
    int m0 = blockIdx.x * 64, n0 = blockIdx.y * 64;
    int tid = threadIdx.x;
    int row_t = tid >> 4, col_t = tid & 15;
    int r = tid >> 2, k4 = (tid & 3) << 2;

    float acc[4][4];
#pragma unroll
    for (int i = 0; i < 4; i++)
#pragma unroll
        for (int j = 0; j < 4; j++) acc[i][j] = 0.f;

    for (int kb = 0; kb < Kc; kb += 16) {
        float4 av = *(const float4*)(A + (size_t)(m0 + r) * Kc + kb + k4);
        As[k4 + 0][r] = av.x; As[k4 + 1][r] = av.y;
        As[k4 + 2][r] = av.z; As[k4 + 3][r] = av.w;
        float4 wv = *(const float4*)(W + (size_t)(n0 + r) * Kc + kb + k4);
        Bs[k4 + 0][r] = wv.x; Bs[k4 + 1][r] = wv.y;
        Bs[k4 + 2][r] = wv.z; Bs[k4 + 3][r] = wv.w;
        __syncthreads();
#pragma unroll
        for (int k = 0; k < 16; k++) {
            float4 a4 = *(const float4*)&As[k][row_t * 4];
            float4 b4 = *(const float4*)&Bs[k][col_t * 4];
            float a[4] = {a4.x, a4.y, a4.z, a4.w};
            float bb[4] = {b4.x, b4.y, b4.z, b4.w};
#pragma unroll
            for (int i = 0; i < 4; i++)
#pragma unroll
                for (int j = 0; j < 4; j++) acc[i][j] += a[i] * bb[j];
        }
        __syncthreads();
    }
#pragma unroll
    for (int i = 0; i < 4; i++) {
        int m = m0 + row_t * 4 + i;
        float vals[4];
#pragma unroll
        for (int j = 0; j < 4; j++) {
            int col = n0 + col_t * 4 + j;
            float val = acc[i][j];
            if (mode & 1) val += bias[col];
            if (mode & 4) val += res[(size_t)m * Nc + col];
            if (mode & 2) val = fmaxf(val, 0.f);
            vals[j] = val;
        }
        *(float4*)(C + (size_t)m * Nc + n0 + col_t * 4) =
            make_float4(vals[0], vals[1], vals[2], vals[3]);
    }
}

// ---------------- logits + softmax(over slots) + partial rowsums ----------------
// grid (NBLK, B); block 128 (thread per n)
__global__ __launch_bounds__(128) void logits_softmax_kernel(
    const float* __restrict__ q, const float* __restrict__ kmat,
    float* __restrict__ attn, float* __restrict__ partsum)
{
    int b = blockIdx.y;
    int nblk = blockIdx.x;
    int tid = threadIdx.x;
    int n = nblk * 128 + tid;

    __shared__ float4 qs[Kk][64];
    const float4* qb = (const float4*)(q + (size_t)b * Kk * Dd);
    for (int i = tid; i < Kk * 64; i += 128) qs[i >> 6][i & 63] = qb[i];
    __syncthreads();

    const float4* kr = (const float4*)(kmat + ((size_t)b * Nn + n) * Dd);
    float l[Kk];
#pragma unroll
    for (int s = 0; s < Kk; s++) l[s] = 0.f;
    for (int d4 = 0; d4 < 64; d4++) {
        float4 kv = kr[d4];
#pragma unroll
        for (int s = 0; s < Kk; s++) {
            float4 qv = qs[s][d4];
            l[s] += qv.x * kv.x + qv.y * kv.y + qv.z * kv.z + qv.w * kv.w;
        }
    }
    float mx = -1e30f;
#pragma unroll
    for (int s = 0; s < Kk; s++) { l[s] *= 0.0625f; mx = fmaxf(mx, l[s]); }
    float sum = 0.f;
#pragma unroll
    for (int s = 0; s < Kk; s++) { l[s] = expf(l[s] - mx); sum += l[s]; }
    float inv = 1.0f / sum;
#pragma unroll
    for (int s = 0; s < Kk; s++) {
        l[s] *= inv;
        attn[((size_t)b * Kk + s) * Nn + n] = l[s];
    }
    // per-block partial sums over n (for attn_norm), deterministic
    __shared__ float red2[Kk][4];
    int warp = tid >> 5, lane = tid & 31;
#pragma unroll
    for (int s = 0; s < Kk; s++) {
        float w = warp_sum(l[s]);
        if (lane == 0) red2[s][warp] = w;
    }
    __syncthreads();
    if (tid < Kk) {
        float s4 = red2[tid][0] + red2[tid][1] + red2[tid][2] + red2[tid][3];
        partsum[(b * Kk + tid) * NBLK + nblk] = s4;
    }
}

// grid 8, block 128 -> g_invsum
__global__ void invsum_kernel() {
    int i = blockIdx.x * 128 + threadIdx.x;
    if (i < BK_TOT) {
        float s = 0.f;
#pragma unroll
        for (int j = 0; j < NBLK; j++) s += g_part[i * NBLK + j];
        g_invsum[i] = 1.0f / (s + 1e-8f);
    }
}

// ---------------- updates = attn_norm @ v, split over 8 n-chunks ----------------
// grid (8, B); block 256 (thread = d)
__global__ __launch_bounds__(256) void updates_partial_kernel(
    const float* __restrict__ attn, const float* __restrict__ v)
{
    int b = blockIdx.y, chunk = blockIdx.x;
    int d = threadIdx.x;
    __shared__ float as[Kk][128];
    __shared__ float inv[Kk];
    if (d < Kk) inv[d] = g_invsum[b * Kk + d];
    float acc[Kk];
#pragma unroll
    for (int s = 0; s < Kk; s++) acc[s] = 0.f;
    int nbase = chunk * 512;
    for (int nt = 0; nt < 512; nt += 128) {
        __syncthreads();
        for (int i = d; i < Kk * 128; i += 256) {
            int s = i >> 7, nn = i & 127;
            as[s][nn] = attn[((size_t)b * Kk + s) * Nn + nbase + nt + nn] * inv[s];
        }
        __syncthreads();
#pragma unroll 4
        for (int j = 0; j < 128; j++) {
            float vv = v[((size_t)b * Nn + nbase + nt + j) * Dd + d];
#pragma unroll
            for (int s = 0; s < Kk; s++) acc[s] += as[s][j] * vv;
        }
    }
    float* p = g_updpart + (size_t)chunk * (BK_TOT * Dd) + (size_t)(b * Kk) * Dd + d;
#pragma unroll
    for (int s = 0; s < Kk; s++) p[s * Dd] = acc[s];
}

// grid 960, block 256
__global__ void updates_reduce_kernel() {
    int i = blockIdx.x * 256 + threadIdx.x;
    float s = 0.f;
#pragma unroll
    for (int c = 0; c < 8; c++) s += g_updpart[(size_t)c * (BK_TOT * Dd) + i];
    g_updates[i] = s;
}

// ---------------- GRU gates ----------------
// grid 960, block 256
__global__ void gru_gate_kernel() {
    int i = blockIdx.x * 256 + threadIdx.x;  // < BK_TOT*Dd
    int row = i >> 8, d = i & 255;
    const float* gi = g_gi + (size_t)row * 768;
    const float* gh = g_gh + (size_t)row * 768;
    float r = sigmoidf_(gi[d] + gh[d]);
    float z = sigmoidf_(gi[256 + d] + gh[256 + d]);
    float nn = tanhf(gi[512 + d] + r * gh[512 + d]);
    float h = g_slots_prev[i];
    g_slots[i] = (1.0f - z) * nn + z * h;
}

// ---------------- copy ----------------
__global__ void copy_kernel(const float* __restrict__ src, float* __restrict__ dst, int n) {
    int i = blockIdx.x * 256 + threadIdx.x;
    if (i < n) dst[i] = src[i];
}

// ---------------- host orchestration ----------------
extern "C" void kernel_launch(void* const* d_in, const int* in_sizes, int n_in,
                              void* d_out, int out_size) {
    const float* inputs        = (const float*)d_in[0];
    const float* slot_noise    = (const float*)d_in[1];
    const float* slots_mu      = (const float*)d_in[2];
    const float* slots_logsig  = (const float*)d_in[3];
    const float* Wq            = (const float*)d_in[4];
    const float* Wk            = (const float*)d_in[5];
    const float* Wv            = (const float*)d_in[6];
    const float* w_ih          = (const float*)d_in[7];
    const float* w_hh          = (const float*)d_in[8];
    const float* b_ih          = (const float*)d_in[9];
    const float* b_hh          = (const float*)d_in[10];
    const float* mlp_w1        = (const float*)d_in[11];
    const float* mlp_b1        = (const float*)d_in[12];
    const float* mlp_w2        = (const float*)d_in[13];
    const float* mlp_b2        = (const float*)d_in[14];
    const float* ln_in_w       = (const float*)d_in[15];
    const float* ln_in_b       = (const float*)d_in[16];
    const float* ln_s_w        = (const float*)d_in[17];
    const float* ln_s_b        = (const float*)d_in[18];
    const float* ln_m_w        = (const float*)d_in[19];
    const float* ln_m_b        = (const float*)d_in[20];
    float* out = (float*)d_out;

    float *p_k, *p_v, *p_attn, *p_part, *p_sln, *p_q, *p_slots, *p_prev,
          *p_upd, *p_gi, *p_gh, *p_h1;
    cudaGetSymbolAddress((void**)&p_k, g_k);
    cudaGetSymbolAddress((void**)&p_v, g_v);
    cudaGetSymbolAddress((void**)&p_attn, g_attn);
    cudaGetSymbolAddress((void**)&p_part, g_part);
    cudaGetSymbolAddress((void**)&p_sln, g_sln);
    cudaGetSymbolAddress((void**)&p_q, g_q);
    cudaGetSymbolAddress((void**)&p_slots, g_slots);
    cudaGetSymbolAddress((void**)&p_prev, g_slots_prev);
    cudaGetSymbolAddress((void**)&p_upd, g_updates);
    cudaGetSymbolAddress((void**)&p_gi, g_gi);
    cudaGetSymbolAddress((void**)&p_gh, g_gh);
    cudaGetSymbolAddress((void**)&p_h1, g_h1);

    // input LN stats + fused-LN K/V projections
    ln_stats_kernel<<<BN_TOT / 8, dim3(32, 8)>>>(inputs);
    kv_gemm_kernel<<<dim3(BN_TOT / 64, 2), 256>>>(inputs, Wk, ln_in_w, ln_in_b, p_k);
    kv_gemm_kernel<<<dim3(BN_TOT / 64, 2), 256>>>(inputs, Wv, ln_in_w, ln_in_b, p_v);
    slots_init_kernel<<<BK_TOT, 256>>>(slots_mu, slots_logsig, slot_noise);

    for (int it = 0; it < 3; it++) {
        copy_kernel<<<960, 256>>>(p_slots, p_prev, BK_TOT * Dd);
        ln_apply_kernel<<<120, dim3(32, 8)>>>(p_slots, p_sln, ln_s_w, ln_s_b, BK_TOT);
        small_gemm_kernel<<<dim3(15, 4), 256>>>(p_sln, Wq, nullptr, nullptr, p_q, 256, 256, 0);
        logits_softmax_kernel<<<dim3(NBLK, Bb), 128>>>(p_q, p_k, p_attn, p_part);
        invsum_kernel<<<8, 128>>>();
        updates_partial_kernel<<<dim3(8, Bb), 256>>>(p_attn, p_v);
        updates_reduce_kernel<<<960, 256>>>();
        small_gemm_kernel<<<dim3(15, 12), 256>>>(p_upd, w_ih, b_ih, nullptr, p_gi, 256, 768, 1);
        small_gemm_kernel<<<dim3(15, 12), 256>>>(p_prev, w_hh, b_hh, nullptr, p_gh, 256, 768, 1);
        gru_gate_kernel<<<960, 256>>>();
        ln_apply_kernel<<<120, dim3(32, 8)>>>(p_slots, p_sln, ln_m_w, ln_m_b, BK_TOT);
        small_gemm_kernel<<<dim3(15, 8), 256>>>(p_sln, mlp_w1, mlp_b1, nullptr, p_h1, 256, 512, 1 | 2);
        small_gemm_kernel<<<dim3(15, 4), 256>>>(p_h1, mlp_w2, mlp_b2, p_slots, p_slots, 512, 256, 1 | 4);
    }

    // final attention
    ln_apply_kernel<<<120, dim3(32, 8)>>>(p_slots, p_sln, ln_s_w, ln_s_b, BK_TOT);
    small_gemm_kernel<<<dim3(15, 4), 256>>>(p_sln, Wq, nullptr, nullptr, p_q, 256, 256, 0);
    logits_softmax_kernel<<<dim3(NBLK, Bb), 128>>>(p_q, p_k, out + BK_TOT * Dd, p_part);
    copy_kernel<<<960, 256>>>(p_slots, out, BK_TOT * Dd);
}

// round 3
// speedup vs baseline: 1.5439x; 1.5439x over previous
#include <cuda_runtime.h>
#include <cuda_bf16.h>
#include <math.h>
#include <stdint.h>

// SlotAttention on GB300 — Round 2: KV projection GEMMs on mma.sync (HMMA
// bf16 x3 precision-compensated, fp32 register accumulate). tcgen05 is not
// compilable under this harness's compute_103 PTX target.

#define Bb 64
#define Nn 4096
#define Dd 256
#define Kk 15
#define Hh 512
#define BN_TOT (Bb * Nn)   // 262144
#define BK_TOT (Bb * Kk)   // 960
#define NBLK 32

// ---------------- scratch (static device memory) ----------------
__device__ __nv_bfloat16 g_xhi[(size_t)BN_TOT * Dd];  // 128 MiB
__device__ __nv_bfloat16 g_xlo[(size_t)BN_TOT * Dd];  // 128 MiB
__device__ __nv_bfloat16 g_whi[2 * Dd * Dd];          // Wk|Wv hi
__device__ __nv_bfloat16 g_wlo[2 * Dd * Dd];          // Wk|Wv lo
__device__ float g_k[(size_t)BN_TOT * Dd];            // 256 MiB
__device__ float g_v[(size_t)BN_TOT * Dd];            // 256 MiB
__device__ float g_slots[BK_TOT * Dd];
__device__ float g_slots_prev[BK_TOT * Dd];
__device__ float g_sln[BK_TOT * Dd];
__device__ float g_q[BK_TOT * Dd];
__device__ float g_attn[(size_t)Bb * Kk * Nn];
__device__ float g_part[Bb * Kk * NBLK];
__device__ float g_invsum[BK_TOT];
__device__ float g_updpart[8 * BK_TOT * Dd];
__device__ float g_updates[BK_TOT * Dd];
__device__ float g_gi[BK_TOT * 3 * Dd];
__device__ float g_gh[BK_TOT * 3 * Dd];
__device__ float g_h1[BK_TOT * Hh];

// ---------------- helpers ----------------
__device__ __forceinline__ float warp_sum(float v) {
#pragma unroll
    for (int o = 16; o > 0; o >>= 1) v += __shfl_xor_sync(0xffffffffu, v, o);
    return v;
}
__device__ __forceinline__ float sigmoidf_(float x) { return 1.0f / (1.0f + expf(-x)); }

__device__ __forceinline__ uint32_t smem_u32(const void* p) {
    uint32_t a;
    asm("{ .reg .u64 t; cvta.to.shared.u64 t, %1; cvt.u32.u64 %0, t; }" : "=r"(a) : "l"(p));
    return a;
}
__device__ __forceinline__ void ldsm_x4(uint32_t& r0, uint32_t& r1, uint32_t& r2, uint32_t& r3,
                                        uint32_t addr) {
    asm volatile("ldmatrix.sync.aligned.m8n8.x4.shared.b16 {%0,%1,%2,%3}, [%4];"
                 : "=r"(r0), "=r"(r1), "=r"(r2), "=r"(r3) : "r"(addr));
}
__device__ __forceinline__ void mma_bf16(float* c, uint32_t a0, uint32_t a1, uint32_t a2,
                                         uint32_t a3, uint32_t b0, uint32_t b1) {
    asm volatile(
        "mma.sync.aligned.m16n8k16.row.col.f32.bf16.bf16.f32 "
        "{%0,%1,%2,%3}, {%4,%5,%6,%7}, {%8,%9}, {%0,%1,%2,%3};"
        : "+f"(c[0]), "+f"(c[1]), "+f"(c[2]), "+f"(c[3])
        : "r"(a0), "r"(a1), "r"(a2), "r"(a3), "r"(b0), "r"(b1));
}

// ---------------- fused LN + hi/lo bf16 split of inputs ----------------
// grid BN_TOT/8, block (32,8)
__global__ void ln_split_kernel(const float* __restrict__ x,
                                const float* __restrict__ w, const float* __restrict__ b) {
    int row = blockIdx.x * 8 + threadIdx.y;
    int lane = threadIdx.x;
    const float* xr = x + (size_t)row * Dd;
    float v[8];
    float s = 0.f, s2 = 0.f;
#pragma unroll
    for (int j = 0; j < 8; j++) {
        v[j] = xr[j * 32 + lane];
        s += v[j]; s2 += v[j] * v[j];
    }
    s = warp_sum(s); s2 = warp_sum(s2);
    float m = s * (1.0f / 256.0f);
    float rs = rsqrtf(s2 * (1.0f / 256.0f) - m * m + 1e-5f);
#pragma unroll
    for (int j = 0; j < 8; j++) {
        int d = j * 32 + lane;
        float y = (v[j] - m) * rs * w[d] + b[d];
        __nv_bfloat16 hi = __float2bfloat16(y);
        __nv_bfloat16 lo = __float2bfloat16(y - __bfloat162float(hi));
        g_xhi[(size_t)row * Dd + d] = hi;
        g_xlo[(size_t)row * Dd + d] = lo;
    }
}

// split Wk|Wv into bf16 hi/lo. grid 512, block 256
__global__ void w_split_kernel(const float* __restrict__ Wk, const float* __restrict__ Wv) {
    int i = blockIdx.x * 256 + threadIdx.x;  // < 131072
    float w = (i < Dd * Dd) ? Wk[i] : Wv[i - Dd * Dd];
    __nv_bfloat16 hi = __float2bfloat16(w);
    g_whi[i] = hi;
    g_wlo[i] = __float2bfloat16(w - __bfloat162float(hi));
}

// ---------------- KV projection GEMM on HMMA (mma.sync bf16 x3) ----------------
// grid (2048, 4): gsel = y>>1, n0 = (y&1)*128. CTA tile 128x128, K chunks of 64.
// 8 warps = 2(m) x 4(n); warp tile 64x32.
#define SROW 72  // smem row stride in bf16 (144B: 16B-aligned, ldmatrix conflict-free)
__global__ __launch_bounds__(256) void kv_mma_kernel(float* __restrict__ outk,
                                                     float* __restrict__ outv) {
    extern __shared__ __nv_bfloat16 sm[];
    __nv_bfloat16* sAh = sm;                 // 128 x SROW
    __nv_bfloat16* sAl = sm + 128 * SROW;
    __nv_bfloat16* sBh = sm + 2 * 128 * SROW;
    __nv_bfloat16* sBl = sm + 3 * 128 * SROW;

    int tid = threadIdx.x;
    int wid = tid >> 5, lane = tid & 31;
    int warp_m = wid >> 2;        // 0..1
    int warp_n = wid & 3;         // 0..3
    int m0 = blockIdx.x * 128;
    int gsel = blockIdx.y >> 1;
    int n0 = (blockIdx.y & 1) << 7;
    float* out = gsel ? outv : outk;
    const __nv_bfloat16* wh = g_whi + gsel * (Dd * Dd);
    const __nv_bfloat16* wl = g_wlo + gsel * (Dd * Dd);

    float acc[4][4][4];
#pragma unroll
    for (int i = 0; i < 4; i++)
#pragma unroll
        for (int j = 0; j < 4; j++)
#pragma unroll
            for (int t = 0; t < 4; t++) acc[i][j][t] = 0.f;

    // ldmatrix source addresses (within warp tile)
    uint32_t sAh_b = smem_u32(sAh), sAl_b = smem_u32(sAl);
    uint32_t sBh_b = smem_u32(sBh), sBl_b = smem_u32(sBl);
    int a_row = warp_m * 64 + (lane & 15);
    int a_koff = (lane >> 4) << 3;            // 0 or 8
    int b_row = warp_n * 32 + (lane & 7) + ((lane >> 4) << 3);
    int b_koff = ((lane >> 3) & 1) << 3;      // 0 or 8

    for (int c = 0; c < 4; c++) {
        int k0 = c * 64;
        if (c) __syncthreads();
        // stage: 128 rows x 64 bf16 per tile; thread loads 4 float4 per tile
#pragma unroll
        for (int t = 0; t < 4; t++) {
            int idx = tid + t * 256;          // < 1024
            int row = idx >> 3, col8 = idx & 7;
            int so = row * SROW + col8 * 8;
            size_t ga = (size_t)(m0 + row) * Dd + k0 + col8 * 8;
            size_t gb = (size_t)(n0 + row) * Dd + k0 + col8 * 8;
            *(float4*)(sAh + so) = *(const float4*)(g_xhi + ga);
            *(float4*)(sAl + so) = *(const float4*)(g_xlo + ga);
            *(float4*)(sBh + so) = *(const float4*)(wh + gb);
            *(float4*)(sBl + so) = *(const float4*)(wl + gb);
        }
        __syncthreads();
#pragma unroll
        for (int ks = 0; ks < 4; ks++) {
            int kk = ks * 16;
            uint32_t ah[4][4], al[4][4];
#pragma unroll
            for (int mt = 0; mt < 4; mt++) {
                uint32_t off = (uint32_t)((a_row + mt * 16) * SROW + kk + a_koff) * 2;
                ldsm_x4(ah[mt][0], ah[mt][1], ah[mt][2], ah[mt][3], sAh_b + off);
                ldsm_x4(al[mt][0], al[mt][1], al[mt][2], al[mt][3], sAl_b + off);
            }
            uint32_t bh[2][4], bl[2][4];
#pragma unroll
            for (int np = 0; np < 2; np++) {
                uint32_t off = (uint32_t)((b_row + np * 16) * SROW + kk + b_koff) * 2;
                ldsm_x4(bh[np][0], bh[np][1], bh[np][2], bh[np][3], sBh_b + off);
                ldsm_x4(bl[np][0], bl[np][1], bl[np][2], bl[np][3], sBl_b + off);
            }
#pragma unroll
            for (int mt = 0; mt < 4; mt++)
#pragma unroll
                for (int np = 0; np < 2; np++)
#pragma unroll
                    for (int h = 0; h < 2; h++) {
                        int nt = np * 2 + h;
                        uint32_t B0h = bh[np][h * 2], B1h = bh[np][h * 2 + 1];
                        uint32_t B0l = bl[np][h * 2], B1l = bl[np][h * 2 + 1];
                        mma_bf16(acc[mt][nt], ah[mt][0], ah[mt][1], ah[mt][2], ah[mt][3], B0h, B1h);
                        mma_bf16(acc[mt][nt], ah[mt][0], ah[mt][1], ah[mt][2], ah[mt][3], B0l, B1l);
                        mma_bf16(acc[mt][nt], al[mt][0], al[mt][1], al[mt][2], al[mt][3], B0h, B1h);
                    }
        }
    }
    // epilogue: thread holds (row=lane/4, col=(lane%4)*2) and row+8
    int er = lane >> 2, ec = (lane & 3) * 2;
#pragma unroll
    for (int mt = 0; mt < 4; mt++) {
        int mrow = m0 + warp_m * 64 + mt * 16 + er;
#pragma unroll
        for (int nt = 0; nt < 4; nt++) {
            int col = n0 + warp_n * 32 + nt * 8 + ec;
            *(float2*)(out + (size_t)mrow * Dd + col) = make_float2(acc[mt][nt][0], acc[mt][nt][1]);
            *(float2*)(out + (size_t)(mrow + 8) * Dd + col) = make_float2(acc[mt][nt][2], acc[mt][nt][3]);
        }
    }
}

// ---------------- slots init ----------------
__global__ void slots_init_kernel(const float* __restrict__ mu,
                                  const float* __restrict__ ls,
                                  const float* __restrict__ noise) {
    int i = blockIdx.x * 256 + threadIdx.x;
    int kd = i % (Kk * Dd);
    g_slots[i] = mu[kd] + expf(ls[kd]) * noise[i];
}

// ---------------- generic row LayerNorm (M x 256) ----------------
__global__ void ln_apply_kernel(const float* __restrict__ x, float* __restrict__ y,
                                const float* __restrict__ w, const float* __restrict__ bb,
                                int M) {
    int row = blockIdx.x * 8 + threadIdx.y;
    if (row >= M) return;
    int lane = threadIdx.x;
    const float* xr = x + (size_t)row * Dd;
    float v[8];
    float s = 0.f, s2 = 0.f;
#pragma unroll
    for (int j = 0; j < 8; j++) {
        v[j] = xr[j * 32 + lane];
        s += v[j]; s2 += v[j] * v[j];
    }
    s = warp_sum(s); s2 = warp_sum(s2);
    float m = s * (1.0f / 256.0f);
    float rs = rsqrtf(s2 * (1.0f / 256.0f) - m * m + 1e-5f);
    float* yr = y + (size_t)row * Dd;
#pragma unroll
    for (int j = 0; j < 8; j++) {
        int dd = j * 32 + lane;
        yr[dd] = (v[j] - m) * rs * w[dd] + bb[dd];
    }
}

// ---------------- small GEMM: C[M][Nc] = A[M][Kc] @ W[Nc][Kc]^T ----------------
__global__ __launch_bounds__(256) void small_gemm_kernel(
    const float* __restrict__ A, const float* __restrict__ W,
    const float* __restrict__ bias, const float* __restrict__ res,
    float* __restrict__ C, int Kc, int Nc, int mode)
{
    __shared__ float As[16][68];
    __shared__ float Bs[16][68];
    int m0 = blockIdx.x * 64, n0 = blockIdx.y * 64;
    int tid = threadIdx.x;
    int row_t = tid >> 4, col_t = tid & 15;
    int r = tid >> 2, k4 = (tid & 3) << 2;

    float acc[4][4];
#pragma unroll
    for (int i = 0; i < 4; i++)
#pragma unroll
        for (int j = 0; j < 4; j++) acc[i][j] = 0.f;

    for (int kb = 0; kb < Kc; kb += 16) {
        float4 av = *(const float4*)(A + (size_t)(m0 + r) * Kc + kb + k4);
        As[k4 + 0][r] = av.x; As[k4 + 1][r] = av.y;
        As[k4 + 2][r] = av.z; As[k4 + 3][r] = av.w;
        float4 wv = *(const float4*)(W + (size_t)(n0 + r) * Kc + kb + k4);
        Bs[k4 + 0][r] = wv.x; Bs[k4 + 1][r] = wv.y;
        Bs[k4 + 2][r] = wv.z; Bs[k4 + 3][r] = wv.w;
        __syncthreads();
#pragma unroll
        for (int k = 0; k < 16; k++) {
            float4 a4 = *(const float4*)&As[k][row_t * 4];
            float4 b4 = *(const float4*)&Bs[k][col_t * 4];
            float a[4] = {a4.x, a4.y, a4.z, a4.w};
            float bb[4] = {b4.x, b4.y, b4.z, b4.w};
#pragma unroll
            for (int i = 0; i < 4; i++)
#pragma unroll
                for (int j = 0; j < 4; j++) acc[i][j] += a[i] * bb[j];
        }
        __syncthreads();
    }
#pragma unroll
    for (int i = 0; i < 4; i++) {
        int m = m0 + row_t * 4 + i;
        float vals[4];
#pragma unroll
        for (int j = 0; j < 4; j++) {
            int col = n0 + col_t * 4 + j;
            float val = acc[i][j];
            if (mode & 1) val += bias[col];
            if (mode & 4) val += res[(size_t)m * Nc + col];
            if (mode & 2) val = fmaxf(val, 0.f);
            vals[j] = val;
        }
        *(float4*)(C + (size_t)m * Nc + n0 + col_t * 4) =
            make_float4(vals[0], vals[1], vals[2], vals[3]);
    }
}

// ---------------- logits + softmax(over slots) + partial rowsums ----------------
__global__ __launch_bounds__(128) void logits_softmax_kernel(
    const float* __restrict__ q, const float* __restrict__ kmat,
    float* __restrict__ attn, float* __restrict__ partsum)
{
    int b = blockIdx.y;
    int nblk = blockIdx.x;
    int tid = threadIdx.x;
    int n = nblk * 128 + tid;

    __shared__ float4 qs[Kk][64];
    const float4* qb = (const float4*)(q + (size_t)b * Kk * Dd);
    for (int i = tid; i < Kk * 64; i += 128) qs[i >> 6][i & 63] = qb[i];
    __syncthreads();

    const float4* kr = (const float4*)(kmat + ((size_t)b * Nn + n) * Dd);
    float l[Kk];
#pragma unroll
    for (int s = 0; s < Kk; s++) l[s] = 0.f;
    for (int d4 = 0; d4 < 64; d4++) {
        float4 kv = kr[d4];
#pragma unroll
        for (int s = 0; s < Kk; s++) {
            float4 qv = qs[s][d4];
            l[s] += qv.x * kv.x + qv.y * kv.y + qv.z * kv.z + qv.w * kv.w;
        }
    }
    float mx = -1e30f;
#pragma unroll
    for (int s = 0; s < Kk; s++) { l[s] *= 0.0625f; mx = fmaxf(mx, l[s]); }
    float sum = 0.f;
#pragma unroll
    for (int s = 0; s < Kk; s++) { l[s] = expf(l[s] - mx); sum += l[s]; }
    float inv = 1.0f / sum;
#pragma unroll
    for (int s = 0; s < Kk; s++) {
        l[s] *= inv;
        attn[((size_t)b * Kk + s) * Nn + n] = l[s];
    }
    __shared__ float red2[Kk][4];
    int warp = tid >> 5, lane = tid & 31;
#pragma unroll
    for (int s = 0; s < Kk; s++) {
        float w = warp_sum(l[s]);
        if (lane == 0) red2[s][warp] = w;
    }
    __syncthreads();
    if (tid < Kk) {
        float s4 = red2[tid][0] + red2[tid][1] + red2[tid][2] + red2[tid][3];
        partsum[(b * Kk + tid) * NBLK + nblk] = s4;
    }
}

__global__ void invsum_kernel() {
    int i = blockIdx.x * 128 + threadIdx.x;
    if (i < BK_TOT) {
        float s = 0.f;
#pragma unroll
        for (int j = 0; j < NBLK; j++) s += g_part[i * NBLK + j];
        g_invsum[i] = 1.0f / (s + 1e-8f);
    }
}

// ---------------- updates = attn_norm @ v, split over 8 n-chunks ----------------
__global__ __launch_bounds__(256) void updates_partial_kernel(
    const float* __restrict__ attn, const float* __restrict__ v)
{
    int b = blockIdx.y, chunk = blockIdx.x;
    int d = threadIdx.x;
    __shared__ float as[Kk][128];
    __shared__ float inv[Kk];
    if (d < Kk) inv[d] = g_invsum[b * Kk + d];
    float acc[Kk];
#pragma unroll
    for (int s = 0; s < Kk; s++) acc[s] = 0.f;
    int nbase = chunk * 512;
    for (int nt = 0; nt < 512; nt += 128) {
        __syncthreads();
        for (int i = d; i < Kk * 128; i += 256) {
            int s = i >> 7, nn = i & 127;
            as[s][nn] = attn[((size_t)b * Kk + s) * Nn + nbase + nt + nn] * inv[s];
        }
        __syncthreads();
#pragma unroll 4
        for (int j = 0; j < 128; j++) {
            float vv = v[((size_t)b * Nn + nbase + nt + j) * Dd + d];
#pragma unroll
            for (int s = 0; s < Kk; s++) acc[s] += as[s][j] * vv;
        }
    }
    float* p = g_updpart + (size_t)chunk * (BK_TOT * Dd) + (size_t)(b * Kk) * Dd + d;
#pragma unroll
    for (int s = 0; s < Kk; s++) p[s * Dd] = acc[s];
}

__global__ void updates_reduce_kernel() {
    int i = blockIdx.x * 256 + threadIdx.x;
    float s = 0.f;
#pragma unroll
    for (int c = 0; c < 8; c++) s += g_updpart[(size_t)c * (BK_TOT * Dd) + i];
    g_updates[i] = s;
}

// ---------------- GRU gates ----------------
__global__ void gru_gate_kernel() {
    int i = blockIdx.x * 256 + threadIdx.x;
    int row = i >> 8, d = i & 255;
    const float* gi = g_gi + (size_t)row * 768;
    const float* gh = g_gh + (size_t)row * 768;
    float r = sigmoidf_(gi[d] + gh[d]);
    float z = sigmoidf_(gi[256 + d] + gh[256 + d]);
    float nn = tanhf(gi[512 + d] + r * gh[512 + d]);
    float h = g_slots_prev[i];
    g_slots[i] = (1.0f - z) * nn + z * h;
}

__global__ void copy_kernel(const float* __restrict__ src, float* __restrict__ dst, int n) {
    int i = blockIdx.x * 256 + threadIdx.x;
    if (i < n) dst[i] = src[i];
}

// ---------------- host orchestration ----------------
extern "C" void kernel_launch(void* const* d_in, const int* in_sizes, int n_in,
                              void* d_out, int out_size) {
    const float* inputs        = (const float*)d_in[0];
    const float* slot_noise    = (const float*)d_in[1];
    const float* slots_mu      = (const float*)d_in[2];
    const float* slots_logsig  = (const float*)d_in[3];
    const float* Wq            = (const float*)d_in[4];
    const float* Wk            = (const float*)d_in[5];
    const float* Wv            = (const float*)d_in[6];
    const float* w_ih          = (const float*)d_in[7];
    const float* w_hh          = (const float*)d_in[8];
    const float* b_ih          = (const float*)d_in[9];
    const float* b_hh          = (const float*)d_in[10];
    const float* mlp_w1        = (const float*)d_in[11];
    const float* mlp_b1        = (const float*)d_in[12];
    const float* mlp_w2        = (const float*)d_in[13];
    const float* mlp_b2        = (const float*)d_in[14];
    const float* ln_in_w       = (const float*)d_in[15];
    const float* ln_in_b       = (const float*)d_in[16];
    const float* ln_s_w        = (const float*)d_in[17];
    const float* ln_s_b        = (const float*)d_in[18];
    const float* ln_m_w        = (const float*)d_in[19];
    const float* ln_m_b        = (const float*)d_in[20];
    float* out = (float*)d_out;

    float *p_k, *p_v, *p_attn, *p_part, *p_sln, *p_q, *p_slots, *p_prev,
          *p_upd, *p_gi, *p_gh, *p_h1;
    cudaGetSymbolAddress((void**)&p_k, g_k);
    cudaGetSymbolAddress((void**)&p_v, g_v);
    cudaGetSymbolAddress((void**)&p_attn, g_attn);
    cudaGetSymbolAddress((void**)&p_part, g_part);
    cudaGetSymbolAddress((void**)&p_sln, g_sln);
    cudaGetSymbolAddress((void**)&p_q, g_q);
    cudaGetSymbolAddress((void**)&p_slots, g_slots);
    cudaGetSymbolAddress((void**)&p_prev, g_slots_prev);
    cudaGetSymbolAddress((void**)&p_upd, g_updates);
    cudaGetSymbolAddress((void**)&p_gi, g_gi);
    cudaGetSymbolAddress((void**)&p_gh, g_gh);
    cudaGetSymbolAddress((void**)&p_h1, g_h1);

    const int kv_smem = 4 * 128 * SROW * 2;  // 73728 bytes
    cudaFuncSetAttribute(kv_mma_kernel, cudaFuncAttributeMaxDynamicSharedMemorySize, kv_smem);

    // LN + bf16 hi/lo split, weight split, HMMA KV projections
    ln_split_kernel<<<BN_TOT / 8, dim3(32, 8)>>>(inputs, ln_in_w, ln_in_b);
    w_split_kernel<<<512, 256>>>(Wk, Wv);
    kv_mma_kernel<<<dim3(2048, 4), 256, kv_smem>>>(p_k, p_v);
    slots_init_kernel<<<BK_TOT, 256>>>(slots_mu, slots_logsig, slot_noise);

    for (int it = 0; it < 3; it++) {
        copy_kernel<<<960, 256>>>(p_slots, p_prev, BK_TOT * Dd);
        ln_apply_kernel<<<120, dim3(32, 8)>>>(p_slots, p_sln, ln_s_w, ln_s_b, BK_TOT);
        small_gemm_kernel<<<dim3(15, 4), 256>>>(p_sln, Wq, nullptr, nullptr, p_q, 256, 256, 0);
        logits_softmax_kernel<<<dim3(NBLK, Bb), 128>>>(p_q, p_k, p_attn, p_part);
        invsum_kernel<<<8, 128>>>();
        updates_partial_kernel<<<dim3(8, Bb), 256>>>(p_attn, p_v);
        updates_reduce_kernel<<<960, 256>>>();
        small_gemm_kernel<<<dim3(15, 12), 256>>>(p_upd, w_ih, b_ih, nullptr, p_gi, 256, 768, 1);
        small_gemm_kernel<<<dim3(15, 12), 256>>>(p_prev, w_hh, b_hh, nullptr, p_gh, 256, 768, 1);
        gru_gate_kernel<<<960, 256>>>();
        ln_apply_kernel<<<120, dim3(32, 8)>>>(p_slots, p_sln, ln_m_w, ln_m_b, BK_TOT);
        small_gemm_kernel<<<dim3(15, 8), 256>>>(p_sln, mlp_w1, mlp_b1, nullptr, p_h1, 256, 512, 1 | 2);
        small_gemm_kernel<<<dim3(15, 4), 256>>>(p_h1, mlp_w2, mlp_b2, p_slots, p_slots, 512, 256, 1 | 4);
    }

    ln_apply_kernel<<<120, dim3(32, 8)>>>(p_slots, p_sln, ln_s_w, ln_s_b, BK_TOT);
    small_gemm_kernel<<<dim3(15, 4), 256>>>(p_sln, Wq, nullptr, nullptr, p_q, 256, 256, 0);
    logits_softmax_kernel<<<dim3(NBLK, Bb), 128>>>(p_q, p_k, out + BK_TOT * Dd, p_part);
    copy_kernel<<<960, 256>>>(p_slots, out, BK_TOT * Dd);
}

// round 4
// speedup vs baseline: 2.1941x; 1.4211x over previous
#include <cuda_runtime.h>
#include <math.h>
#include <stdint.h>

// SlotAttention on GB300 — Round 3: eliminate KV projection GEMMs entirely.
//   logits = (q·Wk)·x̂ᵀ      (fold Wq,Wk into Wqk = Wqᵀ·Wk, once)
//   gi     = (attn·x̂)·(w_ih·Wv)ᵀ   (fold Wv into W_iv = w_ih·Wv, once)
// Only x̂ = LN(inputs) is materialized (fp32). All fp32.

#define Bb 64
#define Nn 4096
#define Dd 256
#define Kk 15
#define Hh 512
#define BN_TOT (Bb * Nn)   // 262144
#define BK_TOT (Bb * Kk)   // 960
#define NBLK 32

// ---------------- scratch (static device memory) ----------------
__device__ float g_xln[(size_t)BN_TOT * Dd];   // 256 MiB LN(inputs)
__device__ float g_wqk[Dd * Dd];               // [e][d] layout for A@Wᵀ gemm
__device__ float g_wiv[3 * Dd * Dd];           // [g][e] = w_ih·Wv
__device__ float g_slots[BK_TOT * Dd];
__device__ float g_slots_prev[BK_TOT * Dd];
__device__ float g_sln[BK_TOT * Dd];
__device__ float g_q[BK_TOT * Dd];             // q' = sln·Wqk
__device__ float g_attn[(size_t)Bb * Kk * Nn];
__device__ float g_part[Bb * Kk * NBLK];
__device__ float g_invsum[BK_TOT];
__device__ float g_updpart[8 * BK_TOT * Dd];
__device__ float g_updates[BK_TOT * Dd];       // u' = attn_norm·x̂
__device__ float g_gi[BK_TOT * 3 * Dd];
__device__ float g_gh[BK_TOT * 3 * Dd];
__device__ float g_h1[BK_TOT * Hh];

// ---------------- helpers ----------------
__device__ __forceinline__ float warp_sum(float v) {
#pragma unroll
    for (int o = 16; o > 0; o >>= 1) v += __shfl_xor_sync(0xffffffffu, v, o);
    return v;
}
__device__ __forceinline__ float sigmoidf_(float x) { return 1.0f / (1.0f + expf(-x)); }

// ---------------- generic row LayerNorm (M x 256) ----------------
__global__ void ln_apply_kernel(const float* __restrict__ x, float* __restrict__ y,
                                const float* __restrict__ w, const float* __restrict__ bb,
                                int M) {
    int row = blockIdx.x * 8 + threadIdx.y;
    if (row >= M) return;
    int lane = threadIdx.x;
    const float* xr = x + (size_t)row * Dd;
    float v[8];
    float s = 0.f, s2 = 0.f;
#pragma unroll
    for (int j = 0; j < 8; j++) {
        v[j] = xr[j * 32 + lane];
        s += v[j]; s2 += v[j] * v[j];
    }
    s = warp_sum(s); s2 = warp_sum(s2);
    float m = s * (1.0f / 256.0f);
    float rs = rsqrtf(s2 * (1.0f / 256.0f) - m * m + 1e-5f);
    float* yr = y + (size_t)row * Dd;
#pragma unroll
    for (int j = 0; j < 8; j++) {
        int dd = j * 32 + lane;
        yr[dd] = (v[j] - m) * rs * w[dd] + bb[dd];
    }
}

// ---------------- precompute: C[e][d] = sum_j X[j][e] * Y[j][d]  (XᵀY) ----------------
__global__ __launch_bounds__(256) void atb_kernel(const float* __restrict__ X,
                                                  const float* __restrict__ Y,
                                                  float* __restrict__ C) {
    __shared__ float Xs[16][68];
    __shared__ float Ys[16][68];
    int e0 = blockIdx.x * 64, d0 = blockIdx.y * 64;
    int tid = threadIdx.x;
    int row_t = tid >> 4, col_t = tid & 15;
    int jr = tid >> 4, c4 = (tid & 15) << 2;

    float acc[4][4];
#pragma unroll
    for (int i = 0; i < 4; i++)
#pragma unroll
        for (int j = 0; j < 4; j++) acc[i][j] = 0.f;

    for (int jb = 0; jb < 256; jb += 16) {
        float4 xv = *(const float4*)(X + (size_t)(jb + jr) * Dd + e0 + c4);
        Xs[jr][c4 + 0] = xv.x; Xs[jr][c4 + 1] = xv.y;
        Xs[jr][c4 + 2] = xv.z; Xs[jr][c4 + 3] = xv.w;
        float4 yv = *(const float4*)(Y + (size_t)(jb + jr) * Dd + d0 + c4);
        Ys[jr][c4 + 0] = yv.x; Ys[jr][c4 + 1] = yv.y;
        Ys[jr][c4 + 2] = yv.z; Ys[jr][c4 + 3] = yv.w;
        __syncthreads();
#pragma unroll
        for (int k = 0; k < 16; k++) {
#pragma unroll
            for (int i = 0; i < 4; i++)
#pragma unroll
                for (int j = 0; j < 4; j++)
                    acc[i][j] += Xs[k][row_t * 4 + i] * Ys[k][col_t * 4 + j];
        }
        __syncthreads();
    }
#pragma unroll
    for (int i = 0; i < 4; i++)
#pragma unroll
        for (int j = 0; j < 4; j++)
            C[(size_t)(e0 + row_t * 4 + i) * Dd + d0 + col_t * 4 + j] = acc[i][j];
}

// ---------------- precompute: C[g][e] = sum_d A[g][d] * B[d][e]  (A·B) ----------------
__global__ __launch_bounds__(256) void ab_kernel(const float* __restrict__ A,
                                                 const float* __restrict__ B,
                                                 float* __restrict__ C) {
    __shared__ float As[16][68];
    __shared__ float Bs[16][68];
    int g0 = blockIdx.x * 64, e0 = blockIdx.y * 64;
    int tid = threadIdx.x;
    int row_t = tid >> 4, col_t = tid & 15;
    int r = tid >> 2, k4 = (tid & 3) << 2;
    int jr = tid >> 4, c4 = (tid & 15) << 2;

    float acc[4][4];
#pragma unroll
    for (int i = 0; i < 4; i++)
#pragma unroll
        for (int j = 0; j < 4; j++) acc[i][j] = 0.f;

    for (int db = 0; db < 256; db += 16) {
        float4 av = *(const float4*)(A + (size_t)(g0 + r) * Dd + db + k4);
        As[k4 + 0][r] = av.x; As[k4 + 1][r] = av.y;
        As[k4 + 2][r] = av.z; As[k4 + 3][r] = av.w;
        float4 bv = *(const float4*)(B + (size_t)(db + jr) * Dd + e0 + c4);
        Bs[jr][c4 + 0] = bv.x; Bs[jr][c4 + 1] = bv.y;
        Bs[jr][c4 + 2] = bv.z; Bs[jr][c4 + 3] = bv.w;
        __syncthreads();
#pragma unroll
        for (int k = 0; k < 16; k++) {
#pragma unroll
            for (int i = 0; i < 4; i++)
#pragma unroll
                for (int j = 0; j < 4; j++)
                    acc[i][j] += As[k][row_t * 4 + i] * Bs[k][col_t * 4 + j];
        }
        __syncthreads();
    }
#pragma unroll
    for (int i = 0; i < 4; i++)
#pragma unroll
        for (int j = 0; j < 4; j++)
            C[(size_t)(g0 + row_t * 4 + i) * Dd + e0 + col_t * 4 + j] = acc[i][j];
}

// ---------------- slots init ----------------
__global__ void slots_init_kernel(const float* __restrict__ mu,
                                  const float* __restrict__ ls,
                                  const float* __restrict__ noise) {
    int i = blockIdx.x * 256 + threadIdx.x;
    int kd = i % (Kk * Dd);
    g_slots[i] = mu[kd] + expf(ls[kd]) * noise[i];
}

// ---------------- small GEMM: C[M][Nc] = A[M][Kc] @ W[Nc][Kc]^T ----------------
__global__ __launch_bounds__(256) void small_gemm_kernel(
    const float* __restrict__ A, const float* __restrict__ W,
    const float* __restrict__ bias, const float* __restrict__ res,
    float* __restrict__ C, int Kc, int Nc, int mode)
{
    __shared__ float As[16][68];
    __shared__ float Bs[16][68];
    int m0 = blockIdx.x * 64, n0 = blockIdx.y * 64;
    int tid = threadIdx.x;
    int row_t = tid >> 4, col_t = tid & 15;
    int r = tid >> 2, k4 = (tid & 3) << 2;

    float acc[4][4];
#pragma unroll
    for (int i = 0; i < 4; i++)
#pragma unroll
        for (int j = 0; j < 4; j++) acc[i][j] = 0.f;

    for (int kb = 0; kb < Kc; kb += 16) {
        float4 av = *(const float4*)(A + (size_t)(m0 + r) * Kc + kb + k4);
        As[k4 + 0][r] = av.x; As[k4 + 1][r] = av.y;
        As[k4 + 2][r] = av.z; As[k4 + 3][r] = av.w;
        float4 wv = *(const float4*)(W + (size_t)(n0 + r) * Kc + kb + k4);
        Bs[k4 + 0][r] = wv.x; Bs[k4 + 1][r] = wv.y;
        Bs[k4 + 2][r] = wv.z; Bs[k4 + 3][r] = wv.w;
        __syncthreads();
#pragma unroll
        for (int k = 0; k < 16; k++) {
            float4 a4 = *(const float4*)&As[k][row_t * 4];
            float4 b4 = *(const float4*)&Bs[k][col_t * 4];
            float a[4] = {a4.x, a4.y, a4.z, a4.w};
            float bb[4] = {b4.x, b4.y, b4.z, b4.w};
#pragma unroll
            for (int i = 0; i < 4; i++)
#pragma unroll
                for (int j = 0; j < 4; j++) acc[i][j] += a[i] * bb[j];
        }
        __syncthreads();
    }
#pragma unroll
    for (int i = 0; i < 4; i++) {
        int m = m0 + row_t * 4 + i;
        float vals[4];
#pragma unroll
        for (int j = 0; j < 4; j++) {
            int col = n0 + col_t * 4 + j;
            float val = acc[i][j];
            if (mode & 1) val += bias[col];
            if (mode & 4) val += res[(size_t)m * Nc + col];
            if (mode & 2) val = fmaxf(val, 0.f);
            vals[j] = val;
        }
        *(float4*)(C + (size_t)m * Nc + n0 + col_t * 4) =
            make_float4(vals[0], vals[1], vals[2], vals[3]);
    }
}

// ---------------- logits (q'·x̂ᵀ) + softmax(over slots) + partial rowsums ----------------
__global__ __launch_bounds__(128) void logits_softmax_kernel(
    const float* __restrict__ q, const float* __restrict__ xln,
    float* __restrict__ attn, float* __restrict__ partsum)
{
    int b = blockIdx.y;
    int nblk = blockIdx.x;
    int tid = threadIdx.x;
    int n = nblk * 128 + tid;

    __shared__ float4 qs[Kk][64];
    const float4* qb = (const float4*)(q + (size_t)b * Kk * Dd);
    for (int i = tid; i < Kk * 64; i += 128) qs[i >> 6][i & 63] = qb[i];
    __syncthreads();

    const float4* kr = (const float4*)(xln + ((size_t)b * Nn + n) * Dd);
    float l[Kk];
#pragma unroll
    for (int s = 0; s < Kk; s++) l[s] = 0.f;
    for (int d4 = 0; d4 < 64; d4++) {
        float4 kv = kr[d4];
#pragma unroll
        for (int s = 0; s < Kk; s++) {
            float4 qv = qs[s][d4];
            l[s] += qv.x * kv.x + qv.y * kv.y + qv.z * kv.z + qv.w * kv.w;
        }
    }
    float mx = -1e30f;
#pragma unroll
    for (int s = 0; s < Kk; s++) { l[s] *= 0.0625f; mx = fmaxf(mx, l[s]); }
    float sum = 0.f;
#pragma unroll
    for (int s = 0; s < Kk; s++) { l[s] = expf(l[s] - mx); sum += l[s]; }
    float inv = 1.0f / sum;
#pragma unroll
    for (int s = 0; s < Kk; s++) {
        l[s] *= inv;
        attn[((size_t)b * Kk + s) * Nn + n] = l[s];
    }
    __shared__ float red2[Kk][4];
    int warp = tid >> 5, lane = tid & 31;
#pragma unroll
    for (int s = 0; s < Kk; s++) {
        float w = warp_sum(l[s]);
        if (lane == 0) red2[s][warp] = w;
    }
    __syncthreads();
    if (tid < Kk) {
        float s4 = red2[tid][0] + red2[tid][1] + red2[tid][2] + red2[tid][3];
        partsum[(b * Kk + tid) * NBLK + nblk] = s4;
    }
}

__global__ void invsum_kernel() {
    int i = blockIdx.x * 128 + threadIdx.x;
    if (i < BK_TOT) {
        float s = 0.f;
#pragma unroll
        for (int j = 0; j < NBLK; j++) s += g_part[i * NBLK + j];
        g_invsum[i] = 1.0f / (s + 1e-8f);
    }
}

// ---------------- u' = attn_norm @ x̂, split over 8 n-chunks ----------------
__global__ __launch_bounds__(256) void updates_partial_kernel(
    const float* __restrict__ attn, const float* __restrict__ xln)
{
    int b = blockIdx.y, chunk = blockIdx.x;
    int d = threadIdx.x;
    __shared__ float as[Kk][128];
    __shared__ float inv[Kk];
    if (d < Kk) inv[d] = g_invsum[b * Kk + d];
    float acc[Kk];
#pragma unroll
    for (int s = 0; s < Kk; s++) acc[s] = 0.f;
    int nbase = chunk * 512;
    for (int nt = 0; nt < 512; nt += 128) {
        __syncthreads();
        for (int i = d; i < Kk * 128; i += 256) {
            int s = i >> 7, nn = i & 127;
            as[s][nn] = attn[((size_t)b * Kk + s) * Nn + nbase + nt + nn] * inv[s];
        }
        __syncthreads();
#pragma unroll 4
        for (int j = 0; j < 128; j++) {
            float vv = xln[((size_t)b * Nn + nbase + nt + j) * Dd + d];
#pragma unroll
            for (int s = 0; s < Kk; s++) acc[s] += as[s][j] * vv;
        }
    }
    float* p = g_updpart + (size_t)chunk * (BK_TOT * Dd) + (size_t)(b * Kk) * Dd + d;
#pragma unroll
    for (int s = 0; s < Kk; s++) p[s * Dd] = acc[s];
}

__global__ void updates_reduce_kernel() {
    int i = blockIdx.x * 256 + threadIdx.x;
    float s = 0.f;
#pragma unroll
    for (int c = 0; c < 8; c++) s += g_updpart[(size_t)c * (BK_TOT * Dd) + i];
    g_updates[i] = s;
}

// ---------------- GRU gates ----------------
__global__ void gru_gate_kernel() {
    int i = blockIdx.x * 256 + threadIdx.x;
    int row = i >> 8, d = i & 255;
    const float* gi = g_gi + (size_t)row * 768;
    const float* gh = g_gh + (size_t)row * 768;
    float r = sigmoidf_(gi[d] + gh[d]);
    float z = sigmoidf_(gi[256 + d] + gh[256 + d]);
    float nn = tanhf(gi[512 + d] + r * gh[512 + d]);
    float h = g_slots_prev[i];
    g_slots[i] = (1.0f - z) * nn + z * h;
}

__global__ void copy_kernel(const float* __restrict__ src, float* __restrict__ dst, int n) {
    int i = blockIdx.x * 256 + threadIdx.x;
    if (i < n) dst[i] = src[i];
}

// ---------------- host orchestration ----------------
extern "C" void kernel_launch(void* const* d_in, const int* in_sizes, int n_in,
                              void* d_out, int out_size) {
    const float* inputs        = (const float*)d_in[0];
    const float* slot_noise    = (const float*)d_in[1];
    const float* slots_mu      = (const float*)d_in[2];
    const float* slots_logsig  = (const float*)d_in[3];
    const float* Wq            = (const float*)d_in[4];
    const float* Wk            = (const float*)d_in[5];
    const float* Wv            = (const float*)d_in[6];
    const float* w_ih          = (const float*)d_in[7];
    const float* w_hh          = (const float*)d_in[8];
    const float* b_ih          = (const float*)d_in[9];
    const float* b_hh          = (const float*)d_in[10];
    const float* mlp_w1        = (const float*)d_in[11];
    const float* mlp_b1        = (const float*)d_in[12];
    const float* mlp_w2        = (const float*)d_in[13];
    const float* mlp_b2        = (const float*)d_in[14];
    const float* ln_in_w       = (const float*)d_in[15];
    const float* ln_in_b       = (const float*)d_in[16];
    const float* ln_s_w        = (const float*)d_in[17];
    const float* ln_s_b        = (const float*)d_in[18];
    const float* ln_m_w        = (const float*)d_in[19];
    const float* ln_m_b        = (const float*)d_in[20];
    float* out = (float*)d_out;

    float *p_xln, *p_wqk, *p_wiv, *p_attn, *p_part, *p_sln, *p_q, *p_slots,
          *p_prev, *p_upd, *p_gi, *p_gh, *p_h1;
    cudaGetSymbolAddress((void**)&p_xln, g_xln);
    cudaGetSymbolAddress((void**)&p_wqk, g_wqk);
    cudaGetSymbolAddress((void**)&p_wiv, g_wiv);
    cudaGetSymbolAddress((void**)&p_attn, g_attn);
    cudaGetSymbolAddress((void**)&p_part, g_part);
    cudaGetSymbolAddress((void**)&p_sln, g_sln);
    cudaGetSymbolAddress((void**)&p_q, g_q);
    cudaGetSymbolAddress((void**)&p_slots, g_slots);
    cudaGetSymbolAddress((void**)&p_prev, g_slots_prev);
    cudaGetSymbolAddress((void**)&p_upd, g_updates);
    cudaGetSymbolAddress((void**)&p_gi, g_gi);
    cudaGetSymbolAddress((void**)&p_gh, g_gh);
    cudaGetSymbolAddress((void**)&p_h1, g_h1);

    // x̂ = LN(inputs); weight folds; slots init
    ln_apply_kernel<<<BN_TOT / 8, dim3(32, 8)>>>(inputs, p_xln, ln_in_w, ln_in_b, BN_TOT);
    atb_kernel<<<dim3(4, 4), 256>>>(Wk, Wq, p_wqk);        // Wqk[e][d] = Σ_j Wk[j,e]·Wq[j,d]
    ab_kernel<<<dim3(12, 4), 256>>>(w_ih, Wv, p_wiv);      // W_iv[g][e] = Σ_d w_ih[g,d]·Wv[d,e]
    slots_init_kernel<<<BK_TOT, 256>>>(slots_mu, slots_logsig, slot_noise);

    for (int it = 0; it < 3; it++) {
        copy_kernel<<<960, 256>>>(p_slots, p_prev, BK_TOT * Dd);
        ln_apply_kernel<<<120, dim3(32, 8)>>>(p_slots, p_sln, ln_s_w, ln_s_b, BK_TOT);
        small_gemm_kernel<<<dim3(15, 4), 256>>>(p_sln, p_wqk, nullptr, nullptr, p_q, 256, 256, 0);
        logits_softmax_kernel<<<dim3(NBLK, Bb), 128>>>(p_q, p_xln, p_attn, p_part);
        invsum_kernel<<<8, 128>>>();
        updates_partial_kernel<<<dim3(8, Bb), 256>>>(p_attn, p_xln);
        updates_reduce_kernel<<<960, 256>>>();
        small_gemm_kernel<<<dim3(15, 12), 256>>>(p_upd, p_wiv, b_ih, nullptr, p_gi, 256, 768, 1);
        small_gemm_kernel<<<dim3(15, 12), 256>>>(p_prev, w_hh, b_hh, nullptr, p_gh, 256, 768, 1);
        gru_gate_kernel<<<960, 256>>>();
        ln_apply_kernel<<<120, dim3(32, 8)>>>(p_slots, p_sln, ln_m_w, ln_m_b, BK_TOT);
        small_gemm_kernel<<<dim3(15, 8), 256>>>(p_sln, mlp_w1, mlp_b1, nullptr, p_h1, 256, 512, 1 | 2);
        small_gemm_kernel<<<dim3(15, 4), 256>>>(p_h1, mlp_w2, mlp_b2, p_slots, p_slots, 512, 256, 1 | 4);
    }

    // final attention
    ln_apply_kernel<<<120, dim3(32, 8)>>>(p_slots, p_sln, ln_s_w, ln_s_b, BK_TOT);
    small_gemm_kernel<<<dim3(15, 4), 256>>>(p_sln, p_wqk, nullptr, nullptr, p_q, 256, 256, 0);
    logits_softmax_kernel<<<dim3(NBLK, Bb), 128>>>(p_q, p_xln, out + BK_TOT * Dd, p_part);
    copy_kernel<<<960, 256>>>(p_slots, out, BK_TOT * Dd);
}